// round 2
// baseline (speedup 1.0000x reference)
#include <cuda_runtime.h>
#include <math.h>

#define NN 50000
#define EE 800000
#define ET 850000   /* EE + NN self loops */
#define CC 64
#define HC 128
#define NCLS 4
#define EPS_GN 1e-5f

// ---------------- scratch (device globals; no runtime allocation) ----------------
__device__ __align__(16) float g_xl[NN * HC];
__device__ __align__(16) float g_xr[NN * HC];
__device__ __align__(16) float g_h[NN * CC];
__device__ float g_e[ET * 2];
__device__ float g_emax[NN * 2];
__device__ float g_denom[NN * 2];
__device__ int   g_deg[NN];
__device__ int   g_rowptr[NN + 1];
__device__ int   g_cursor[NN];
__device__ int   g_csrc[ET];
__device__ int   g_ceid[ET];
__device__ float g_sum[CC], g_sumsq[CC];
__device__ float g_scale[CC], g_shift[CC];
__device__ __align__(16) float g_Wlf[CC * HC], g_Wrf[CC * HC];
__device__ __align__(16) float g_blf[HC], g_brf[HC];
__device__ float g_W1f[CC * NCLS], g_b1f[NCLS];

// ---------------- helpers ----------------
__device__ __forceinline__ void atomicMaxF(float* addr, float v) {
    if (v >= 0.0f) atomicMax((int*)addr, __float_as_int(v));
    else           atomicMin((unsigned int*)addr, __float_as_uint(v));
}

// ---------------- CSR build ----------------
__global__ void k_zero_deg() {
    int i = blockIdx.x * blockDim.x + threadIdx.x;
    if (i < NN) g_deg[i] = 0;
}

__global__ void k_count(const int* __restrict__ ei) {
    int e = blockIdx.x * blockDim.x + threadIdx.x;
    if (e >= ET) return;
    int dst = (e < EE) ? ei[EE + e] : (e - EE);
    atomicAdd(&g_deg[dst], 1);
}

__global__ void k_scan() {
    __shared__ int sh[1024];
    __shared__ int carry;
    int tid = threadIdx.x;
    if (tid == 0) carry = 0;
    __syncthreads();
    for (int base = 0; base < NN; base += 1024) {
        int i = base + tid;
        int v = (i < NN) ? g_deg[i] : 0;
        sh[tid] = v;
        __syncthreads();
        for (int off = 1; off < 1024; off <<= 1) {
            int t = (tid >= off) ? sh[tid - off] : 0;
            __syncthreads();
            sh[tid] += t;
            __syncthreads();
        }
        if (i < NN) {
            int excl = carry + sh[tid] - v;
            g_rowptr[i] = excl;
            g_cursor[i] = excl;
        }
        int tot = sh[1023];
        __syncthreads();
        if (tid == 0) carry += tot;
        __syncthreads();
    }
    if (tid == 0) g_rowptr[NN] = carry;
}

__global__ void k_scatter(const int* __restrict__ ei) {
    int e = blockIdx.x * blockDim.x + threadIdx.x;
    if (e >= ET) return;
    int src, dst;
    if (e < EE) { src = ei[e]; dst = ei[EE + e]; }
    else        { src = dst = e - EE; }
    int p = atomicAdd(&g_cursor[dst], 1);
    g_csrc[p] = src;
    g_ceid[p] = e;
}

// ---------------- per-layer init ----------------
__global__ void k_layer_init() {
    int i = blockIdx.x * blockDim.x + threadIdx.x;
    if (i < NN * 2) { g_denom[i] = 0.0f; g_emax[i] = -3.0e38f; }
    if (i < CC)     { g_sum[i] = 0.0f; g_sumsq[i] = 0.0f; }
}

// ---------------- GEMM: out[NN,128] = A[NN,K] @ W[K,128] + b ----------------
__global__ void k_gemm(const float* __restrict__ A, const float* __restrict__ W,
                       const float* __restrict__ b, float* __restrict__ out, int K) {
    __shared__ __align__(16) float As[32][65];
    __shared__ __align__(16) float Ws[32][128];
    int tid = threadIdx.x;
    int row0 = blockIdx.x * 64;
    int tc = tid & 31;   // col group: cols tc*4 .. tc*4+3
    int tr = tid >> 5;   // 0..7, rows tr + 8*i
    float acc[8][4];
#pragma unroll
    for (int i = 0; i < 8; i++)
#pragma unroll
        for (int j = 0; j < 4; j++) acc[i][j] = 0.0f;

    for (int k0 = 0; k0 < K; k0 += 32) {
#pragma unroll
        for (int l = 0; l < 8; l++) {           // A tile 64x32
            int idx = tid + l * 256;
            int r = idx >> 5, kk = idx & 31;
            int gr = row0 + r;
            As[kk][r] = (gr < NN) ? A[gr * K + k0 + kk] : 0.0f;
        }
#pragma unroll
        for (int l = 0; l < 16; l++) {          // W tile 32x128
            int idx = tid + l * 256;
            int kk = idx >> 7, cc = idx & 127;
            Ws[kk][cc] = W[(k0 + kk) * 128 + cc];
        }
        __syncthreads();
#pragma unroll
        for (int kk = 0; kk < 32; kk++) {
            float4 w4 = *(const float4*)&Ws[kk][tc * 4];
#pragma unroll
            for (int i = 0; i < 8; i++) {
                float a = As[kk][tr + i * 8];
                acc[i][0] += a * w4.x;
                acc[i][1] += a * w4.y;
                acc[i][2] += a * w4.z;
                acc[i][3] += a * w4.w;
            }
        }
        __syncthreads();
    }
    float4 bb = *(const float4*)&b[tc * 4];
#pragma unroll
    for (int i = 0; i < 8; i++) {
        int gr = row0 + tr + i * 8;
        if (gr < NN) {
            float4 o;
            o.x = acc[i][0] + bb.x;
            o.y = acc[i][1] + bb.y;
            o.z = acc[i][2] + bb.z;
            o.w = acc[i][3] + bb.w;
            *(float4*)&out[gr * 128 + tc * 4] = o;
        }
    }
}

// ---------------- edge attention logits ----------------
__global__ void k_edge_e(const int* __restrict__ ei,
                         const float* __restrict__ xl, const float* __restrict__ xr,
                         const float* __restrict__ att) {
    int w = (blockIdx.x * blockDim.x + threadIdx.x) >> 5;
    int lane = threadIdx.x & 31;
    if (w >= ET) return;
    int src, dst;
    if (w < EE) { src = ei[w]; dst = ei[EE + w]; }
    else        { src = dst = w - EE; }
    float4 a  = *(const float4*)(xl + src * HC + lane * 4);
    float4 bq = *(const float4*)(xr + dst * HC + lane * 4);
    float4 t4 = *(const float4*)(att + lane * 4);
    float p = 0.0f, v;
    v = a.x + bq.x; v = v > 0.0f ? v : 0.2f * v; p += v * t4.x;
    v = a.y + bq.y; v = v > 0.0f ? v : 0.2f * v; p += v * t4.y;
    v = a.z + bq.z; v = v > 0.0f ? v : 0.2f * v; p += v * t4.z;
    v = a.w + bq.w; v = v > 0.0f ? v : 0.2f * v; p += v * t4.w;
    // reduce within each 16-lane half (head 0: lanes 0-15, head 1: lanes 16-31)
    p += __shfl_xor_sync(0xffffffffu, p, 8);
    p += __shfl_xor_sync(0xffffffffu, p, 4);
    p += __shfl_xor_sync(0xffffffffu, p, 2);
    p += __shfl_xor_sync(0xffffffffu, p, 1);
    if (lane == 0)  g_e[2 * w]     = p;
    if (lane == 16) g_e[2 * w + 1] = p;
}

__global__ void k_edge_max(const int* __restrict__ ei) {
    int e = blockIdx.x * blockDim.x + threadIdx.x;
    if (e >= ET) return;
    int dst = (e < EE) ? ei[EE + e] : (e - EE);
    atomicMaxF(&g_emax[2 * dst],     g_e[2 * e]);
    atomicMaxF(&g_emax[2 * dst + 1], g_e[2 * e + 1]);
}

__global__ void k_edge_exp(const int* __restrict__ ei) {
    int e = blockIdx.x * blockDim.x + threadIdx.x;
    if (e >= ET) return;
    int dst = (e < EE) ? ei[EE + e] : (e - EE);
    float m0 = g_emax[2 * dst], m1 = g_emax[2 * dst + 1];
    float v0 = __expf(g_e[2 * e] - m0);
    float v1 = __expf(g_e[2 * e + 1] - m1);
    g_e[2 * e] = v0;
    g_e[2 * e + 1] = v1;
    atomicAdd(&g_denom[2 * dst],     v0);
    atomicAdd(&g_denom[2 * dst + 1], v1);
}

// ---------------- aggregation (CSR by dst, warp per node) ----------------
__global__ void k_aggregate(const float* __restrict__ xl, const float* __restrict__ bias) {
    int node = (blockIdx.x * blockDim.x + threadIdx.x) >> 5;
    int lane = threadIdx.x & 31;
    if (node >= NN) return;
    int s0 = g_rowptr[node], s1 = g_rowptr[node + 1];
    int head = lane >> 4;
    float a0 = 0.0f, a1 = 0.0f, a2 = 0.0f, a3 = 0.0f;
    for (int idx = s0; idx < s1; idx++) {
        int src = g_csrc[idx];
        int eid = g_ceid[idx];
        float wgt = g_e[2 * eid + head];
        float4 v = *(const float4*)(xl + src * HC + lane * 4);
        a0 += wgt * v.x; a1 += wgt * v.y; a2 += wgt * v.z; a3 += wgt * v.w;
    }
    float inv = 1.0f / (g_denom[2 * node + head] + 1e-16f);
    a0 *= inv; a1 *= inv; a2 *= inv; a3 *= inv;
    a0 = 0.5f * (a0 + __shfl_down_sync(0xffffffffu, a0, 16));
    a1 = 0.5f * (a1 + __shfl_down_sync(0xffffffffu, a1, 16));
    a2 = 0.5f * (a2 + __shfl_down_sync(0xffffffffu, a2, 16));
    a3 = 0.5f * (a3 + __shfl_down_sync(0xffffffffu, a3, 16));
    if (lane < 16) {
        float4 bb = *(const float4*)(bias + lane * 4);
        float4 o;
        o.x = a0 + bb.x; o.y = a1 + bb.y; o.z = a2 + bb.z; o.w = a3 + bb.w;
        *(float4*)(g_h + node * CC + lane * 4) = o;
    }
}

// ---------------- GraphNorm stats ----------------
__global__ void k_stats() {
    __shared__ float ss[4][CC], ss2[4][CC];
    int c = threadIdx.x & 63;
    int sub = threadIdx.x >> 6;
    float s = 0.0f, s2 = 0.0f;
    for (int node = blockIdx.x * 4 + sub; node < NN; node += gridDim.x * 4) {
        float v = g_h[node * CC + c];
        s += v; s2 += v * v;
    }
    ss[sub][c] = s; ss2[sub][c] = s2;
    __syncthreads();
    if (threadIdx.x < CC) {
        atomicAdd(&g_sum[c],   ss[0][c] + ss[1][c] + ss[2][c] + ss[3][c]);
        atomicAdd(&g_sumsq[c], ss2[0][c] + ss2[1][c] + ss2[2][c] + ss2[3][c]);
    }
}

__global__ void k_norm_finalize(const float* __restrict__ gamma,
                                const float* __restrict__ beta,
                                const float* __restrict__ a) {
    int c = threadIdx.x;
    if (c >= CC) return;
    float mean = g_sum[c] * (1.0f / NN);
    float ex2  = g_sumsq[c] * (1.0f / NN);
    float ac = a[c];
    float var = ex2 - 2.0f * ac * mean * mean + ac * ac * mean * mean;
    float r = rsqrtf(var + EPS_GN);
    float sc = gamma[c] * r;
    g_scale[c] = sc;
    g_shift[c] = beta[c] - sc * ac * mean;
}

// fold norm (scale/shift) into layer-2 weights: W'[k,j]=s[k]W[k,j]; b'[j]=b[j]+sum_k t[k]W[k,j]
__global__ void k_fold2(const float* __restrict__ Wl, const float* __restrict__ bl,
                        const float* __restrict__ Wr, const float* __restrict__ br) {
    int j = threadIdx.x & 127;
    int which = threadIdx.x >> 7;
    const float* W = which ? Wr : Wl;
    const float* b = which ? br : bl;
    float* Wf = which ? g_Wrf : g_Wlf;
    float* bf = which ? g_brf : g_blf;
    float acc = b[j];
#pragma unroll 8
    for (int k = 0; k < CC; k++) {
        float w = W[k * 128 + j];
        Wf[k * 128 + j] = g_scale[k] * w;
        acc += g_shift[k] * w;
    }
    bf[j] = acc;
}

__global__ void k_fold_final(const float* __restrict__ W1, const float* __restrict__ b1) {
    int c = threadIdx.x;
    if (c >= NCLS) return;
    float acc = b1[c];
#pragma unroll 8
    for (int k = 0; k < CC; k++) {
        float w = W1[k * NCLS + c];
        g_W1f[k * NCLS + c] = g_scale[k] * w;
        acc += g_shift[k] * w;
    }
    g_b1f[c] = acc;
}

// ---------------- classifier + log_softmax ----------------
__global__ void k_classify(float* __restrict__ out) {
    __shared__ float Ws[CC * NCLS];
    __shared__ float bs[NCLS];
    if (threadIdx.x < CC * NCLS) Ws[threadIdx.x] = g_W1f[threadIdx.x];
    if (threadIdx.x < NCLS) bs[threadIdx.x] = g_b1f[threadIdx.x];
    __syncthreads();
    int node = blockIdx.x * blockDim.x + threadIdx.x;
    if (node >= NN) return;
    float l0 = bs[0], l1 = bs[1], l2 = bs[2], l3 = bs[3];
#pragma unroll 8
    for (int k = 0; k < CC; k++) {
        float h = g_h[node * CC + k];
        l0 += h * Ws[k * 4 + 0];
        l1 += h * Ws[k * 4 + 1];
        l2 += h * Ws[k * 4 + 2];
        l3 += h * Ws[k * 4 + 3];
    }
    float m = fmaxf(fmaxf(l0, l1), fmaxf(l2, l3));
    float s = __expf(l0 - m) + __expf(l1 - m) + __expf(l2 - m) + __expf(l3 - m);
    float ls = m + __logf(s);
    float4 o;
    o.x = l0 - ls; o.y = l1 - ls; o.z = l2 - ls; o.w = l3 - ls;
    *(float4*)(out + node * 4) = o;
}

// ---------------- launcher ----------------
extern "C" void kernel_launch(void* const* d_in, const int* in_sizes, int n_in,
                              void* d_out, int out_size) {
    const float* x     = (const float*)d_in[0];
    const int*   ei    = (const int*)d_in[1];
    const float* Wl1   = (const float*)d_in[2];
    const float* bl1   = (const float*)d_in[3];
    const float* Wr1   = (const float*)d_in[4];
    const float* br1   = (const float*)d_in[5];
    const float* att1  = (const float*)d_in[6];
    const float* bias1 = (const float*)d_in[7];
    const float* gng1  = (const float*)d_in[8];
    const float* gnb1  = (const float*)d_in[9];
    const float* gna1  = (const float*)d_in[10];
    const float* Wl2   = (const float*)d_in[11];
    const float* bl2   = (const float*)d_in[12];
    const float* Wr2   = (const float*)d_in[13];
    const float* br2   = (const float*)d_in[14];
    const float* att2  = (const float*)d_in[15];
    const float* bias2 = (const float*)d_in[16];
    const float* gng2  = (const float*)d_in[17];
    const float* gnb2  = (const float*)d_in[18];
    const float* gna2  = (const float*)d_in[19];
    const float* W1    = (const float*)d_in[20];
    const float* b1    = (const float*)d_in[21];
    float* out = (float*)d_out;

    float *p_xl, *p_xr, *p_h, *p_Wlf, *p_blf, *p_Wrf, *p_brf;
    cudaGetSymbolAddress((void**)&p_xl,  g_xl);
    cudaGetSymbolAddress((void**)&p_xr,  g_xr);
    cudaGetSymbolAddress((void**)&p_h,   g_h);
    cudaGetSymbolAddress((void**)&p_Wlf, g_Wlf);
    cudaGetSymbolAddress((void**)&p_blf, g_blf);
    cudaGetSymbolAddress((void**)&p_Wrf, g_Wrf);
    cudaGetSymbolAddress((void**)&p_brf, g_brf);

    const int TB = 256;
    int gN   = (NN + TB - 1) / TB;
    int gE   = (ET + TB - 1) / TB;
    int gEw  = (ET * 32 + TB - 1) / TB;    // warp per edge
    int gNw  = (NN * 32 + TB - 1) / TB;    // warp per node
    int gN2  = (NN * 2 + TB - 1) / TB;
    int gG   = (NN + 63) / 64;

    // CSR build (shared by both layers)
    k_zero_deg<<<gN, TB>>>();
    k_count<<<gE, TB>>>(ei);
    k_scan<<<1, 1024>>>();
    k_scatter<<<gE, TB>>>(ei);

    // ---- layer 1 ----
    k_layer_init<<<gN2, TB>>>();
    k_gemm<<<gG, TB>>>(x, Wl1, bl1, p_xl, 128);
    k_gemm<<<gG, TB>>>(x, Wr1, br1, p_xr, 128);
    k_edge_e<<<gEw, TB>>>(ei, p_xl, p_xr, att1);
    k_edge_max<<<gE, TB>>>(ei);
    k_edge_exp<<<gE, TB>>>(ei);
    k_aggregate<<<gNw, TB>>>(p_xl, bias1);
    k_stats<<<296, TB>>>();
    k_norm_finalize<<<1, 64>>>(gng1, gnb1, gna1);
    k_fold2<<<1, 256>>>(Wl2, bl2, Wr2, br2);

    // ---- layer 2 ----
    k_layer_init<<<gN2, TB>>>();
    k_gemm<<<gG, TB>>>(p_h, p_Wlf, p_blf, p_xl, 64);
    k_gemm<<<gG, TB>>>(p_h, p_Wrf, p_brf, p_xr, 64);
    k_edge_e<<<gEw, TB>>>(ei, p_xl, p_xr, att2);
    k_edge_max<<<gE, TB>>>(ei);
    k_edge_exp<<<gE, TB>>>(ei);
    k_aggregate<<<gNw, TB>>>(p_xl, bias2);
    k_stats<<<296, TB>>>();
    k_norm_finalize<<<1, 64>>>(gng2, gnb2, gna2);
    k_fold_final<<<1, 32>>>(W1, b1);

    k_classify<<<gN, TB>>>(out);
}

// round 3
// speedup vs baseline: 1.3654x; 1.3654x over previous
#include <cuda_runtime.h>
#include <math.h>

#define NN 50000
#define EE 800000
#define ET 850000   /* EE + NN self loops */
#define CC 64
#define HC 128
#define NCLS 4
#define EPS_GN 1e-5f

// ---------------- scratch (device globals; no runtime allocation) ----------------
__device__ __align__(16) float g_xl[NN * HC];
__device__ __align__(16) float g_xr[NN * HC];
__device__ __align__(16) float g_h[NN * CC];
__device__ int   g_deg[NN];
__device__ int   g_rowptr[NN + 1];
__device__ int   g_cursor[NN];
__device__ int   g_csrc[ET];
__device__ float g_sum[CC], g_sumsq[CC];
__device__ float g_scale[CC], g_shift[CC];
__device__ __align__(16) float g_Wlf[CC * HC], g_Wrf[CC * HC];
__device__ __align__(16) float g_blf[HC], g_brf[HC];
__device__ float g_W1f[CC * NCLS], g_b1f[NCLS];

// ---------------- CSR build ----------------
__global__ void k_zero_deg() {
    int i = blockIdx.x * blockDim.x + threadIdx.x;
    if (i < NN) g_deg[i] = 0;
}

__global__ void k_count(const int* __restrict__ ei) {
    int e = blockIdx.x * blockDim.x + threadIdx.x;
    if (e >= ET) return;
    int dst = (e < EE) ? ei[EE + e] : (e - EE);
    atomicAdd(&g_deg[dst], 1);
}

__global__ void k_scan() {
    __shared__ int sh[1024];
    __shared__ int carry;
    int tid = threadIdx.x;
    if (tid == 0) carry = 0;
    __syncthreads();
    for (int base = 0; base < NN; base += 1024) {
        int i = base + tid;
        int v = (i < NN) ? g_deg[i] : 0;
        sh[tid] = v;
        __syncthreads();
        for (int off = 1; off < 1024; off <<= 1) {
            int t = (tid >= off) ? sh[tid - off] : 0;
            __syncthreads();
            sh[tid] += t;
            __syncthreads();
        }
        if (i < NN) {
            int excl = carry + sh[tid] - v;
            g_rowptr[i] = excl;
            g_cursor[i] = excl;
        }
        int tot = sh[1023];
        __syncthreads();
        if (tid == 0) carry += tot;
        __syncthreads();
    }
    if (tid == 0) g_rowptr[NN] = carry;
}

__global__ void k_scatter(const int* __restrict__ ei) {
    int e = blockIdx.x * blockDim.x + threadIdx.x;
    if (e >= ET) return;
    int src, dst;
    if (e < EE) { src = ei[e]; dst = ei[EE + e]; }
    else        { src = dst = e - EE; }
    int p = atomicAdd(&g_cursor[dst], 1);
    g_csrc[p] = src;
}

// ---------------- stats zero ----------------
__global__ void k_zero_stats() {
    int c = threadIdx.x;
    if (c < CC) { g_sum[c] = 0.0f; g_sumsq[c] = 0.0f; }
}

// ---------------- merged GEMM: xl/xr[NN,128] = A[NN,K] @ {Wl,Wr}[K,128] + {bl,br} ----------------
__global__ void k_gemm2(const float* __restrict__ A,
                        const float* __restrict__ Wl, const float* __restrict__ bl,
                        const float* __restrict__ Wr, const float* __restrict__ br,
                        float* __restrict__ outl, float* __restrict__ outr, int K) {
    __shared__ __align__(16) float As[32][65];
    __shared__ __align__(16) float Wsl[32][128];
    __shared__ __align__(16) float Wsr[32][128];
    int tid = threadIdx.x;
    int row0 = blockIdx.x * 64;
    int tc = tid & 31;   // col group: cols tc*4 .. tc*4+3
    int tr = tid >> 5;   // 0..7, rows tr + 8*i
    float accl[8][4], accr[8][4];
#pragma unroll
    for (int i = 0; i < 8; i++)
#pragma unroll
        for (int j = 0; j < 4; j++) { accl[i][j] = 0.0f; accr[i][j] = 0.0f; }

    for (int k0 = 0; k0 < K; k0 += 32) {
#pragma unroll
        for (int l = 0; l < 8; l++) {           // A tile 64x32
            int idx = tid + l * 256;
            int r = idx >> 5, kk = idx & 31;
            int gr = row0 + r;
            As[kk][r] = (gr < NN) ? A[gr * K + k0 + kk] : 0.0f;
        }
#pragma unroll
        for (int l = 0; l < 16; l++) {          // W tiles 32x128
            int idx = tid + l * 256;
            int kk = idx >> 7, cc = idx & 127;
            Wsl[kk][cc] = Wl[(k0 + kk) * 128 + cc];
            Wsr[kk][cc] = Wr[(k0 + kk) * 128 + cc];
        }
        __syncthreads();
#pragma unroll
        for (int kk = 0; kk < 32; kk++) {
            float4 wl = *(const float4*)&Wsl[kk][tc * 4];
            float4 wr = *(const float4*)&Wsr[kk][tc * 4];
#pragma unroll
            for (int i = 0; i < 8; i++) {
                float a = As[kk][tr + i * 8];
                accl[i][0] += a * wl.x;
                accl[i][1] += a * wl.y;
                accl[i][2] += a * wl.z;
                accl[i][3] += a * wl.w;
                accr[i][0] += a * wr.x;
                accr[i][1] += a * wr.y;
                accr[i][2] += a * wr.z;
                accr[i][3] += a * wr.w;
            }
        }
        __syncthreads();
    }
    float4 bbl = *(const float4*)&bl[tc * 4];
    float4 bbr = *(const float4*)&br[tc * 4];
#pragma unroll
    for (int i = 0; i < 8; i++) {
        int gr = row0 + tr + i * 8;
        if (gr < NN) {
            float4 o;
            o.x = accl[i][0] + bbl.x;
            o.y = accl[i][1] + bbl.y;
            o.z = accl[i][2] + bbl.z;
            o.w = accl[i][3] + bbl.w;
            *(float4*)&outl[gr * 128 + tc * 4] = o;
            o.x = accr[i][0] + bbr.x;
            o.y = accr[i][1] + bbr.y;
            o.z = accr[i][2] + bbr.z;
            o.w = accr[i][3] + bbr.w;
            *(float4*)&outr[gr * 128 + tc * 4] = o;
        }
    }
}

// ---------------- fused attention + online softmax + aggregation (warp per node) ----------------
__global__ void k_attn_agg(const float* __restrict__ xl, const float* __restrict__ xr,
                           const float* __restrict__ att, const float* __restrict__ bias) {
    int node = (blockIdx.x * blockDim.x + threadIdx.x) >> 5;
    int lane = threadIdx.x & 31;
    if (node >= NN) return;
    int s0 = g_rowptr[node], s1 = g_rowptr[node + 1];
    float4 t4 = *(const float4*)(att + lane * 4);           // [2,64] flat: half-warp = head
    float4 xq = *(const float4*)(xr + node * HC + lane * 4);
    float runmax = -3.0e38f, denom = 0.0f;
    float a0 = 0.0f, a1 = 0.0f, a2 = 0.0f, a3 = 0.0f;
    for (int idx = s0; idx < s1; idx++) {
        int src = __ldg(&g_csrc[idx]);
        float4 v = *(const float4*)(xl + src * HC + lane * 4);
        float m, p = 0.0f;
        m = v.x + xq.x; m = m > 0.0f ? m : 0.2f * m; p += m * t4.x;
        m = v.y + xq.y; m = m > 0.0f ? m : 0.2f * m; p += m * t4.y;
        m = v.z + xq.z; m = m > 0.0f ? m : 0.2f * m; p += m * t4.z;
        m = v.w + xq.w; m = m > 0.0f ? m : 0.2f * m; p += m * t4.w;
        // reduce within each 16-lane half (head 0: lanes 0-15, head 1: lanes 16-31)
        p += __shfl_xor_sync(0xffffffffu, p, 8);
        p += __shfl_xor_sync(0xffffffffu, p, 4);
        p += __shfl_xor_sync(0xffffffffu, p, 2);
        p += __shfl_xor_sync(0xffffffffu, p, 1);
        float w;
        if (p > runmax) {                 // uniform within each half-warp
            float c = __expf(runmax - p); // first iter: exp(-huge) = 0 (clean)
            a0 *= c; a1 *= c; a2 *= c; a3 *= c; denom *= c;
            runmax = p;
            w = 1.0f;
        } else {
            w = __expf(p - runmax);
        }
        a0 += w * v.x; a1 += w * v.y; a2 += w * v.z; a3 += w * v.w;
        denom += w;
    }
    // runmax ended at the true segment max -> identical normalization to reference
    float inv = 1.0f / (denom + 1e-16f);
    a0 *= inv; a1 *= inv; a2 *= inv; a3 *= inv;
    a0 = 0.5f * (a0 + __shfl_down_sync(0xffffffffu, a0, 16));
    a1 = 0.5f * (a1 + __shfl_down_sync(0xffffffffu, a1, 16));
    a2 = 0.5f * (a2 + __shfl_down_sync(0xffffffffu, a2, 16));
    a3 = 0.5f * (a3 + __shfl_down_sync(0xffffffffu, a3, 16));
    if (lane < 16) {
        float4 bb = *(const float4*)(bias + lane * 4);
        float4 o;
        o.x = a0 + bb.x; o.y = a1 + bb.y; o.z = a2 + bb.z; o.w = a3 + bb.w;
        *(float4*)(g_h + node * CC + lane * 4) = o;
    }
}

// ---------------- GraphNorm stats ----------------
__global__ void k_stats() {
    __shared__ float ss[4][CC], ss2[4][CC];
    int c = threadIdx.x & 63;
    int sub = threadIdx.x >> 6;
    float s = 0.0f, s2 = 0.0f;
    for (int node = blockIdx.x * 4 + sub; node < NN; node += gridDim.x * 4) {
        float v = g_h[node * CC + c];
        s += v; s2 += v * v;
    }
    ss[sub][c] = s; ss2[sub][c] = s2;
    __syncthreads();
    if (threadIdx.x < CC) {
        atomicAdd(&g_sum[c],   ss[0][c] + ss[1][c] + ss[2][c] + ss[3][c]);
        atomicAdd(&g_sumsq[c], ss2[0][c] + ss2[1][c] + ss2[2][c] + ss2[3][c]);
    }
}

__global__ void k_norm_finalize(const float* __restrict__ gamma,
                                const float* __restrict__ beta,
                                const float* __restrict__ a) {
    int c = threadIdx.x;
    if (c >= CC) return;
    float mean = g_sum[c] * (1.0f / NN);
    float ex2  = g_sumsq[c] * (1.0f / NN);
    float ac = a[c];
    float var = ex2 - 2.0f * ac * mean * mean + ac * ac * mean * mean;
    float r = rsqrtf(var + EPS_GN);
    float sc = gamma[c] * r;
    g_scale[c] = sc;
    g_shift[c] = beta[c] - sc * ac * mean;
}

// fold norm (scale/shift) into layer-2 weights: W'[k,j]=s[k]W[k,j]; b'[j]=b[j]+sum_k t[k]W[k,j]
__global__ void k_fold2(const float* __restrict__ Wl, const float* __restrict__ bl,
                        const float* __restrict__ Wr, const float* __restrict__ br) {
    int j = threadIdx.x & 127;
    int which = threadIdx.x >> 7;
    const float* W = which ? Wr : Wl;
    const float* b = which ? br : bl;
    float* Wf = which ? g_Wrf : g_Wlf;
    float* bf = which ? g_brf : g_blf;
    float acc = b[j];
#pragma unroll 8
    for (int k = 0; k < CC; k++) {
        float w = W[k * 128 + j];
        Wf[k * 128 + j] = g_scale[k] * w;
        acc += g_shift[k] * w;
    }
    bf[j] = acc;
}

__global__ void k_fold_final(const float* __restrict__ W1, const float* __restrict__ b1) {
    int c = threadIdx.x;
    if (c >= NCLS) return;
    float acc = b1[c];
#pragma unroll 8
    for (int k = 0; k < CC; k++) {
        float w = W1[k * NCLS + c];
        g_W1f[k * NCLS + c] = g_scale[k] * w;
        acc += g_shift[k] * w;
    }
    g_b1f[c] = acc;
}

// ---------------- classifier + log_softmax ----------------
__global__ void k_classify(float* __restrict__ out) {
    __shared__ float Ws[CC * NCLS];
    __shared__ float bs[NCLS];
    if (threadIdx.x < CC * NCLS) Ws[threadIdx.x] = g_W1f[threadIdx.x];
    if (threadIdx.x < NCLS) bs[threadIdx.x] = g_b1f[threadIdx.x];
    __syncthreads();
    int node = blockIdx.x * blockDim.x + threadIdx.x;
    if (node >= NN) return;
    float l0 = bs[0], l1 = bs[1], l2 = bs[2], l3 = bs[3];
#pragma unroll 8
    for (int k = 0; k < CC; k++) {
        float h = g_h[node * CC + k];
        l0 += h * Ws[k * 4 + 0];
        l1 += h * Ws[k * 4 + 1];
        l2 += h * Ws[k * 4 + 2];
        l3 += h * Ws[k * 4 + 3];
    }
    float m = fmaxf(fmaxf(l0, l1), fmaxf(l2, l3));
    float s = __expf(l0 - m) + __expf(l1 - m) + __expf(l2 - m) + __expf(l3 - m);
    float ls = m + __logf(s);
    float4 o;
    o.x = l0 - ls; o.y = l1 - ls; o.z = l2 - ls; o.w = l3 - ls;
    *(float4*)(out + node * 4) = o;
}

// ---------------- launcher ----------------
extern "C" void kernel_launch(void* const* d_in, const int* in_sizes, int n_in,
                              void* d_out, int out_size) {
    const float* x     = (const float*)d_in[0];
    const int*   ei    = (const int*)d_in[1];
    const float* Wl1   = (const float*)d_in[2];
    const float* bl1   = (const float*)d_in[3];
    const float* Wr1   = (const float*)d_in[4];
    const float* br1   = (const float*)d_in[5];
    const float* att1  = (const float*)d_in[6];
    const float* bias1 = (const float*)d_in[7];
    const float* gng1  = (const float*)d_in[8];
    const float* gnb1  = (const float*)d_in[9];
    const float* gna1  = (const float*)d_in[10];
    const float* Wl2   = (const float*)d_in[11];
    const float* bl2   = (const float*)d_in[12];
    const float* Wr2   = (const float*)d_in[13];
    const float* br2   = (const float*)d_in[14];
    const float* att2  = (const float*)d_in[15];
    const float* bias2 = (const float*)d_in[16];
    const float* gng2  = (const float*)d_in[17];
    const float* gnb2  = (const float*)d_in[18];
    const float* gna2  = (const float*)d_in[19];
    const float* W1    = (const float*)d_in[20];
    const float* b1    = (const float*)d_in[21];
    float* out = (float*)d_out;

    float *p_xl, *p_xr, *p_h, *p_Wlf, *p_blf, *p_Wrf, *p_brf;
    cudaGetSymbolAddress((void**)&p_xl,  g_xl);
    cudaGetSymbolAddress((void**)&p_xr,  g_xr);
    cudaGetSymbolAddress((void**)&p_h,   g_h);
    cudaGetSymbolAddress((void**)&p_Wlf, g_Wlf);
    cudaGetSymbolAddress((void**)&p_blf, g_blf);
    cudaGetSymbolAddress((void**)&p_Wrf, g_Wrf);
    cudaGetSymbolAddress((void**)&p_brf, g_brf);

    const int TB = 256;
    int gN   = (NN + TB - 1) / TB;
    int gE   = (ET + TB - 1) / TB;
    int gNw  = (NN * 32 + TB - 1) / TB;    // warp per node
    int gG   = (NN + 63) / 64;

    // CSR build (shared by both layers)
    k_zero_deg<<<gN, TB>>>();
    k_count<<<gE, TB>>>(ei);
    k_scan<<<1, 1024>>>();
    k_scatter<<<gE, TB>>>(ei);

    // ---- layer 1 ----
    k_zero_stats<<<1, 64>>>();
    k_gemm2<<<gG, TB>>>(x, Wl1, bl1, Wr1, br1, p_xl, p_xr, 128);
    k_attn_agg<<<gNw, TB>>>(p_xl, p_xr, att1, bias1);
    k_stats<<<296, TB>>>();
    k_norm_finalize<<<1, 64>>>(gng1, gnb1, gna1);
    k_fold2<<<1, 256>>>(Wl2, bl2, Wr2, br2);

    // ---- layer 2 ----
    k_zero_stats<<<1, 64>>>();
    k_gemm2<<<gG, TB>>>(p_h, p_Wlf, p_blf, p_Wrf, p_brf, p_xl, p_xr, 64);
    k_attn_agg<<<gNw, TB>>>(p_xl, p_xr, att2, bias2);
    k_stats<<<296, TB>>>();
    k_norm_finalize<<<1, 64>>>(gng2, gnb2, gna2);
    k_fold_final<<<1, 32>>>(W1, b1);

    k_classify<<<gN, TB>>>(out);
}

// round 4
// speedup vs baseline: 1.4931x; 1.0935x over previous
#include <cuda_runtime.h>
#include <math.h>

#define NN 50000
#define EE 800000
#define ET 850000   /* EE + NN self loops */
#define CC 64
#define HC 128
#define NCLS 4
#define EPS_GN 1e-5f
#define SCAN_B 1024
#define SCAN_NB ((NN + SCAN_B - 1) / SCAN_B)   /* 49 */

// ---------------- scratch (device globals; no runtime allocation) ----------------
__device__ __align__(16) float g_xl[NN * HC];
__device__ __align__(16) float g_xr[NN * HC];
__device__ __align__(16) float g_h[NN * CC];
__device__ int   g_deg[NN];
__device__ int   g_rowptr[NN + 1];
__device__ int   g_cursor[NN];
__device__ int   g_csrc[ET];
__device__ int   g_scanval[64];
__device__ int   g_scanflag[64];
__device__ float g_sum[CC], g_sumsq[CC];
__device__ float g_scale[CC], g_shift[CC];
__device__ __align__(16) float g_Wlf[CC * HC], g_Wrf[CC * HC];
__device__ __align__(16) float g_blf[HC], g_brf[HC];
__device__ float g_W1f[CC * NCLS], g_b1f[NCLS];

// ---------------- CSR build ----------------
__global__ void k_zero_deg() {
    int i = blockIdx.x * blockDim.x + threadIdx.x;
    if (i < NN) g_deg[i] = 0;
    if (i < 64) { g_scanflag[i] = 0; }
}

__global__ void k_count(const int* __restrict__ ei) {
    int e = blockIdx.x * blockDim.x + threadIdx.x;
    if (e >= ET) return;
    int dst = (e < EE) ? ei[EE + e] : (e - EE);
    atomicAdd(&g_deg[dst], 1);
}

// chained (decoupled) scan: 49 blocks, all resident simultaneously
__global__ void k_scan_chained() {
    __shared__ int sh[SCAN_B];
    __shared__ int s_prefix;
    int b = blockIdx.x, tid = threadIdx.x;
    int i = b * SCAN_B + tid;
    int v = (i < NN) ? g_deg[i] : 0;
    sh[tid] = v;
    __syncthreads();
#pragma unroll
    for (int off = 1; off < SCAN_B; off <<= 1) {
        int t = (tid >= off) ? sh[tid - off] : 0;
        __syncthreads();
        sh[tid] += t;
        __syncthreads();
    }
    if (tid == 0) {
        int prefix = 0;
        if (b > 0) {
            while (atomicAdd(&g_scanflag[b - 1], 0) == 0) { }
            prefix = g_scanval[b - 1];
        }
        s_prefix = prefix;
        g_scanval[b] = prefix + sh[SCAN_B - 1];
        __threadfence();
        atomicExch(&g_scanflag[b], 1);
        if (b == SCAN_NB - 1) g_rowptr[NN] = prefix + sh[SCAN_B - 1];
    }
    __syncthreads();
    if (i < NN) {
        int excl = s_prefix + sh[tid] - v;
        g_rowptr[i] = excl;
        g_cursor[i] = excl;
    }
    if (b == 0 && tid < CC) { g_sum[tid] = 0.0f; g_sumsq[tid] = 0.0f; }
}

__global__ void k_scatter(const int* __restrict__ ei) {
    int e = blockIdx.x * blockDim.x + threadIdx.x;
    if (e >= ET) return;
    int src, dst;
    if (e < EE) { src = ei[e]; dst = ei[EE + e]; }
    else        { src = dst = e - EE; }
    int p = atomicAdd(&g_cursor[dst], 1);
    g_csrc[p] = src;
}

// ---------------- merged GEMM: xl/xr[NN,128] = A[NN,K] @ {Wl,Wr}[K,128] + {bl,br} ----------------
__global__ void k_gemm2(const float* __restrict__ A,
                        const float* __restrict__ Wl, const float* __restrict__ bl,
                        const float* __restrict__ Wr, const float* __restrict__ br,
                        float* __restrict__ outl, float* __restrict__ outr, int K) {
    __shared__ __align__(16) float As[32][65];
    __shared__ __align__(16) float Wsl[32][128];
    __shared__ __align__(16) float Wsr[32][128];
    int tid = threadIdx.x;
    int row0 = blockIdx.x * 64;
    int tc = tid & 31;   // col group: cols tc*4 .. tc*4+3
    int tr = tid >> 5;   // 0..7, rows tr + 8*i
    float accl[8][4], accr[8][4];
#pragma unroll
    for (int i = 0; i < 8; i++)
#pragma unroll
        for (int j = 0; j < 4; j++) { accl[i][j] = 0.0f; accr[i][j] = 0.0f; }

    for (int k0 = 0; k0 < K; k0 += 32) {
#pragma unroll
        for (int l = 0; l < 8; l++) {           // A tile 64x32
            int idx = tid + l * 256;
            int r = idx >> 5, kk = idx & 31;
            int gr = row0 + r;
            As[kk][r] = (gr < NN) ? A[gr * K + k0 + kk] : 0.0f;
        }
#pragma unroll
        for (int l = 0; l < 16; l++) {          // W tiles 32x128
            int idx = tid + l * 256;
            int kk = idx >> 7, cc = idx & 127;
            Wsl[kk][cc] = Wl[(k0 + kk) * 128 + cc];
            Wsr[kk][cc] = Wr[(k0 + kk) * 128 + cc];
        }
        __syncthreads();
#pragma unroll
        for (int kk = 0; kk < 32; kk++) {
            float4 wl = *(const float4*)&Wsl[kk][tc * 4];
            float4 wr = *(const float4*)&Wsr[kk][tc * 4];
#pragma unroll
            for (int i = 0; i < 8; i++) {
                float a = As[kk][tr + i * 8];
                accl[i][0] += a * wl.x;
                accl[i][1] += a * wl.y;
                accl[i][2] += a * wl.z;
                accl[i][3] += a * wl.w;
                accr[i][0] += a * wr.x;
                accr[i][1] += a * wr.y;
                accr[i][2] += a * wr.z;
                accr[i][3] += a * wr.w;
            }
        }
        __syncthreads();
    }
    float4 bbl = *(const float4*)&bl[tc * 4];
    float4 bbr = *(const float4*)&br[tc * 4];
#pragma unroll
    for (int i = 0; i < 8; i++) {
        int gr = row0 + tr + i * 8;
        if (gr < NN) {
            float4 o;
            o.x = accl[i][0] + bbl.x;
            o.y = accl[i][1] + bbl.y;
            o.z = accl[i][2] + bbl.z;
            o.w = accl[i][3] + bbl.w;
            *(float4*)&outl[gr * 128 + tc * 4] = o;
            o.x = accr[i][0] + bbr.x;
            o.y = accr[i][1] + bbr.y;
            o.z = accr[i][2] + bbr.z;
            o.w = accr[i][3] + bbr.w;
            *(float4*)&outr[gr * 128 + tc * 4] = o;
        }
    }
}

// ---- fused attention + online softmax + aggregation + GraphNorm stats (warp per node) ----
__global__ void k_attn_agg(const float* __restrict__ xl, const float* __restrict__ xr,
                           const float* __restrict__ att, const float* __restrict__ bias) {
    __shared__ float s_sum[CC], s_sq[CC];
    int tid = threadIdx.x;
    if (tid < CC) { s_sum[tid] = 0.0f; s_sq[tid] = 0.0f; }
    __syncthreads();

    int node = (blockIdx.x * blockDim.x + tid) >> 5;
    int lane = tid & 31;
    bool active = node < NN;
    int s0 = 0, s1 = 0;
    if (active) { s0 = g_rowptr[node]; s1 = g_rowptr[node + 1]; }
    float4 t4 = *(const float4*)(att + lane * 4);           // [2,64] flat: half-warp = head
    float4 xq = make_float4(0.f, 0.f, 0.f, 0.f);
    if (active) xq = *(const float4*)(xr + node * HC + lane * 4);

    float runmax = -3.0e38f, denom = 0.0f;
    float a0 = 0.0f, a1 = 0.0f, a2 = 0.0f, a3 = 0.0f;

    float4 v_n = make_float4(0.f, 0.f, 0.f, 0.f);
    if (s0 < s1) {
        int sn = __ldg(&g_csrc[s0]);
        v_n = *(const float4*)(xl + sn * HC + lane * 4);
    }
    for (int idx = s0; idx < s1; idx++) {
        float4 v = v_n;
        if (idx + 1 < s1) {                     // prefetch next edge's row
            int sn = __ldg(&g_csrc[idx + 1]);
            v_n = *(const float4*)(xl + sn * HC + lane * 4);
        }
        float m, p = 0.0f;
        m = v.x + xq.x; m = m > 0.0f ? m : 0.2f * m; p += m * t4.x;
        m = v.y + xq.y; m = m > 0.0f ? m : 0.2f * m; p += m * t4.y;
        m = v.z + xq.z; m = m > 0.0f ? m : 0.2f * m; p += m * t4.z;
        m = v.w + xq.w; m = m > 0.0f ? m : 0.2f * m; p += m * t4.w;
        // reduce within each 16-lane half (head 0: lanes 0-15, head 1: lanes 16-31)
        p += __shfl_xor_sync(0xffffffffu, p, 8);
        p += __shfl_xor_sync(0xffffffffu, p, 4);
        p += __shfl_xor_sync(0xffffffffu, p, 2);
        p += __shfl_xor_sync(0xffffffffu, p, 1);
        float w;
        if (p > runmax) {                 // uniform within each half-warp
            float c = __expf(runmax - p); // first iter: exp(-huge) = 0 (clean)
            a0 *= c; a1 *= c; a2 *= c; a3 *= c; denom *= c;
            runmax = p;
            w = 1.0f;
        } else {
            w = __expf(p - runmax);
        }
        a0 += w * v.x; a1 += w * v.y; a2 += w * v.z; a3 += w * v.w;
        denom += w;
    }
    // runmax ended at the true segment max -> identical normalization to reference
    float inv = 1.0f / (denom + 1e-16f);
    a0 *= inv; a1 *= inv; a2 *= inv; a3 *= inv;
    a0 = 0.5f * (a0 + __shfl_down_sync(0xffffffffu, a0, 16));
    a1 = 0.5f * (a1 + __shfl_down_sync(0xffffffffu, a1, 16));
    a2 = 0.5f * (a2 + __shfl_down_sync(0xffffffffu, a2, 16));
    a3 = 0.5f * (a3 + __shfl_down_sync(0xffffffffu, a3, 16));
    if (active && lane < 16) {
        float4 bb = *(const float4*)(bias + lane * 4);
        float4 o;
        o.x = a0 + bb.x; o.y = a1 + bb.y; o.z = a2 + bb.z; o.w = a3 + bb.w;
        *(float4*)(g_h + node * CC + lane * 4) = o;
        int c4 = lane * 4;
        atomicAdd(&s_sum[c4 + 0], o.x); atomicAdd(&s_sq[c4 + 0], o.x * o.x);
        atomicAdd(&s_sum[c4 + 1], o.y); atomicAdd(&s_sq[c4 + 1], o.y * o.y);
        atomicAdd(&s_sum[c4 + 2], o.z); atomicAdd(&s_sq[c4 + 2], o.z * o.z);
        atomicAdd(&s_sum[c4 + 3], o.w); atomicAdd(&s_sq[c4 + 3], o.w * o.w);
    }
    __syncthreads();
    if (tid < CC) {
        atomicAdd(&g_sum[tid], s_sum[tid]);
        atomicAdd(&g_sumsq[tid], s_sq[tid]);
    }
}

__global__ void k_norm_finalize(const float* __restrict__ gamma,
                                const float* __restrict__ beta,
                                const float* __restrict__ a) {
    int c = threadIdx.x;
    if (c >= CC) return;
    float mean = g_sum[c] * (1.0f / NN);
    float ex2  = g_sumsq[c] * (1.0f / NN);
    float ac = a[c];
    float var = ex2 - 2.0f * ac * mean * mean + ac * ac * mean * mean;
    float r = rsqrtf(var + EPS_GN);
    float sc = gamma[c] * r;
    g_scale[c] = sc;
    g_shift[c] = beta[c] - sc * ac * mean;
    g_sum[c] = 0.0f;     // pre-zero for next layer's fused stats
    g_sumsq[c] = 0.0f;
}

// fold norm (scale/shift) into layer-2 weights: W'[k,j]=s[k]W[k,j]; b'[j]=b[j]+sum_k t[k]W[k,j]
__global__ void k_fold2(const float* __restrict__ Wl, const float* __restrict__ bl,
                        const float* __restrict__ Wr, const float* __restrict__ br) {
    int j = threadIdx.x & 127;
    int which = threadIdx.x >> 7;
    const float* W = which ? Wr : Wl;
    const float* b = which ? br : bl;
    float* Wf = which ? g_Wrf : g_Wlf;
    float* bf = which ? g_brf : g_blf;
    float acc = b[j];
#pragma unroll 8
    for (int k = 0; k < CC; k++) {
        float w = W[k * 128 + j];
        Wf[k * 128 + j] = g_scale[k] * w;
        acc += g_shift[k] * w;
    }
    bf[j] = acc;
}

__global__ void k_fold_final(const float* __restrict__ W1, const float* __restrict__ b1) {
    int c = threadIdx.x;
    if (c >= NCLS) return;
    float acc = b1[c];
#pragma unroll 8
    for (int k = 0; k < CC; k++) {
        float w = W1[k * NCLS + c];
        g_W1f[k * NCLS + c] = g_scale[k] * w;
        acc += g_shift[k] * w;
    }
    g_b1f[c] = acc;
}

// ---------------- classifier + log_softmax ----------------
__global__ void k_classify(float* __restrict__ out) {
    __shared__ float Ws[CC * NCLS];
    __shared__ float bs[NCLS];
    if (threadIdx.x < CC * NCLS) Ws[threadIdx.x] = g_W1f[threadIdx.x];
    if (threadIdx.x < NCLS) bs[threadIdx.x] = g_b1f[threadIdx.x];
    __syncthreads();
    int node = blockIdx.x * blockDim.x + threadIdx.x;
    if (node >= NN) return;
    float l0 = bs[0], l1 = bs[1], l2 = bs[2], l3 = bs[3];
#pragma unroll 8
    for (int k = 0; k < CC; k++) {
        float h = g_h[node * CC + k];
        l0 += h * Ws[k * 4 + 0];
        l1 += h * Ws[k * 4 + 1];
        l2 += h * Ws[k * 4 + 2];
        l3 += h * Ws[k * 4 + 3];
    }
    float m = fmaxf(fmaxf(l0, l1), fmaxf(l2, l3));
    float s = __expf(l0 - m) + __expf(l1 - m) + __expf(l2 - m) + __expf(l3 - m);
    float ls = m + __logf(s);
    float4 o;
    o.x = l0 - ls; o.y = l1 - ls; o.z = l2 - ls; o.w = l3 - ls;
    *(float4*)(out + node * 4) = o;
}

// ---------------- launcher ----------------
extern "C" void kernel_launch(void* const* d_in, const int* in_sizes, int n_in,
                              void* d_out, int out_size) {
    const float* x     = (const float*)d_in[0];
    const int*   ei    = (const int*)d_in[1];
    const float* Wl1   = (const float*)d_in[2];
    const float* bl1   = (const float*)d_in[3];
    const float* Wr1   = (const float*)d_in[4];
    const float* br1   = (const float*)d_in[5];
    const float* att1  = (const float*)d_in[6];
    const float* bias1 = (const float*)d_in[7];
    const float* gng1  = (const float*)d_in[8];
    const float* gnb1  = (const float*)d_in[9];
    const float* gna1  = (const float*)d_in[10];
    const float* Wl2   = (const float*)d_in[11];
    const float* bl2   = (const float*)d_in[12];
    const float* Wr2   = (const float*)d_in[13];
    const float* br2   = (const float*)d_in[14];
    const float* att2  = (const float*)d_in[15];
    const float* bias2 = (const float*)d_in[16];
    const float* gng2  = (const float*)d_in[17];
    const float* gnb2  = (const float*)d_in[18];
    const float* gna2  = (const float*)d_in[19];
    const float* W1    = (const float*)d_in[20];
    const float* b1    = (const float*)d_in[21];
    float* out = (float*)d_out;

    float *p_xl, *p_xr, *p_h, *p_Wlf, *p_blf, *p_Wrf, *p_brf;
    cudaGetSymbolAddress((void**)&p_xl,  g_xl);
    cudaGetSymbolAddress((void**)&p_xr,  g_xr);
    cudaGetSymbolAddress((void**)&p_h,   g_h);
    cudaGetSymbolAddress((void**)&p_Wlf, g_Wlf);
    cudaGetSymbolAddress((void**)&p_blf, g_blf);
    cudaGetSymbolAddress((void**)&p_Wrf, g_Wrf);
    cudaGetSymbolAddress((void**)&p_brf, g_brf);

    const int TB = 256;
    int gN   = (NN + TB - 1) / TB;
    int gE   = (ET + TB - 1) / TB;
    int gNw  = (NN * 32 + TB - 1) / TB;    // warp per node
    int gG   = (NN + 63) / 64;

    // CSR build (shared by both layers)
    k_zero_deg<<<gN, TB>>>();                                          // launch 0
    k_count<<<gE, TB>>>(ei);                                           // launch 1
    k_scan_chained<<<SCAN_NB, SCAN_B>>>();                             // launch 2
    k_scatter<<<gE, TB>>>(ei);                                         // launch 3

    // ---- layer 1 ----
    k_gemm2<<<gG, TB>>>(x, Wl1, bl1, Wr1, br1, p_xl, p_xr, 128);       // launch 4
    k_attn_agg<<<gNw, TB>>>(p_xl, p_xr, att1, bias1);                  // launch 5 (profiled)
    k_norm_finalize<<<1, 64>>>(gng1, gnb1, gna1);
    k_fold2<<<1, 256>>>(Wl2, bl2, Wr2, br2);

    // ---- layer 2 ----
    k_gemm2<<<gG, TB>>>(p_h, p_Wlf, p_blf, p_Wrf, p_brf, p_xl, p_xr, 64);
    k_attn_agg<<<gNw, TB>>>(p_xl, p_xr, att2, bias2);
    k_norm_finalize<<<1, 64>>>(gng2, gnb2, gna2);
    k_fold_final<<<1, 32>>>(W1, b1);

    k_classify<<<gN, TB>>>(out);
}